// round 16
// baseline (speedup 1.0000x reference)
#include <cuda_runtime.h>
#include <math.h>

#define BATCH   8
#define NPTS    4096
#define SPLITS  16
#define SCAND   (NPTS / SPLITS)   // 256 candidates per split = one tile
#define TILE    256
#define BLOCK   64
#define Q       8                 // queries per thread
#define QPB     (BLOCK * Q)       // 512 queries per block
#define QCHUNKS_MAIN (NPTS / QPB) // 8
#define CBLOCK  128               // combine threads per block
#define QCHUNKS (NPTS / CBLOCK)   // 32 combine chunks per (dir,b)
#define NCOMBINE (QCHUNKS * BATCH * 2)  // 512 combine blocks
#define QTOTAL  (2 * BATCH * NPTS)      // 65536 queries overall

// Scratch (static device arrays; no allocation allowed)
// Transposed layout: g_pack[split][global_query] -> combine's split-min loads
// are lane-coalesced (256B/instr) instead of 32-sector scatters.
__device__ unsigned long long g_pack[SPLITS * QTOTAL];
__device__ float g_part[NCOMBINE];   // per-chunk |diff|^5 sums
__device__ unsigned int g_ticket;    // zero-init, self-resetting

// Order-preserving float -> uint32 map (monotone for all finite floats).
static __device__ __forceinline__ unsigned int fmap(float f) {
    unsigned int u = __float_as_uint(f);
    return (u & 0x80000000u) ? ~u : (u | 0x80000000u);
}
static __device__ __forceinline__ float funmap(unsigned int m) {
    return __uint_as_float((m & 0x80000000u) ? (m & 0x7FFFFFFFu) : ~m);
}

// Bit-exact rescore (identical fmaf sequence everywhere it is evaluated).
static __device__ __forceinline__ float score(float cx, float cy, float cz,
                                              float nqx, float nqy, float nqz) {
    float h = 0.5f * fmaf(cx, cx, fmaf(cy, cy, cz * cz));
    return fmaf(nqx, cx, fmaf(nqy, cy, fmaf(nqz, cz, h)));
}

// Main: each thread owns 8 queries, scans this block's 256-candidate split.
// Objective: h - q.c, h = 0.5|c|^2 (|q|^2 dropped, argmin-invariant).
// Writes one packed u64 per (query, split): [mapped score | 32-group base].
// BYTE-IDENTICAL to the proven round-14 kernel (fma-pipe floor, ~46us).
__global__ void __launch_bounds__(BLOCK) chamfer_main(
    const float* __restrict__ x, const float* __restrict__ y)
{
    const int qchunk = blockIdx.x >> 4;    // 0..7
    const int split  = blockIdx.x & 15;    // 0..15
    const int b   = blockIdx.y;
    const int dir = blockIdx.z;
    const float* q  = (dir == 0) ? x : y;
    const float* db = (dir == 0) ? y : x;
    const float* qb  = q  + (size_t)b * NPTS * 3;
    const float* dbb = db + (size_t)b * NPTS * 3;

    float nqx[Q], nqy[Q], nqz[Q];
    #pragma unroll
    for (int k = 0; k < Q; k++) {
        const int qi = qchunk * QPB + threadIdx.x + k * BLOCK;
        nqx[k] = -qb[qi*3+0];
        nqy[k] = -qb[qi*3+1];
        nqz[k] = -qb[qi*3+2];
    }

    __shared__ float4 sh[TILE];

    const int cbeg = split * SCAND;
    #pragma unroll
    for (int k = 0; k < TILE / BLOCK; k++) {
        const int cl = threadIdx.x + k * BLOCK;
        const int c  = cbeg + cl;
        float cx = dbb[c*3+0], cy = dbb[c*3+1], cz = dbb[c*3+2];
        sh[cl] = make_float4(cx, cy, cz, 0.5f * fmaf(cx, cx, fmaf(cy, cy, cz * cz)));
    }
    __syncthreads();

    float best[Q];
    int   base[Q];
    #pragma unroll
    for (int k = 0; k < Q; k++) { best[k] = 3.4e38f; base[k] = cbeg; }

    #pragma unroll
    for (int g = 0; g < TILE / 32; g++) {
        float prev[Q];
        #pragma unroll
        for (int k = 0; k < Q; k++) prev[k] = best[k];
        #pragma unroll 8
        for (int j = 0; j < 32; j++) {
            float4 c = sh[g * 32 + j];   // broadcast LDS.128, feeds 8 chains
            #pragma unroll
            for (int k = 0; k < Q; k++)
                best[k] = fminf(best[k],
                    fmaf(nqx[k], c.x, fmaf(nqy[k], c.y, fmaf(nqz[k], c.z, c.w))));
        }
        const int gb = cbeg + g * 32;
        #pragma unroll
        for (int k = 0; k < Q; k++)
            if (best[k] < prev[k]) base[k] = gb;   // strict <: earliest group wins
    }

    const int qs = (dir * BATCH + b) * NPTS;
    #pragma unroll
    for (int k = 0; k < Q; k++) {
        const int qi = qchunk * QPB + threadIdx.x + k * BLOCK;
        g_pack[(size_t)split * QTOTAL + qs + qi] =
            ((unsigned long long)fmap(best[k]) << 32) | (unsigned int)base[k];
    }
}

// Combine: coalesced split-min (16 independent LDG.64, min-TREE dependency;
// equal score bits -> smaller base = earlier split = first-min). Ballot rescan
// with PREFETCH DEPTH 2: round ws resolves with data loaded at ws-2, so the
// ~250cyc LDG latency is fully covered and rounds run at the sync-chain floor.
// NN coords extracted in-round via shfl from the first-hit lane. Per-chunk
// reduction; LAST block (ticket) folds out[0].
__global__ void __launch_bounds__(CBLOCK) combine_kernel(
    const float* __restrict__ x, const float* __restrict__ y,
    float* __restrict__ out)
{
    const int chunk = blockIdx.x;
    const int b   = blockIdx.y;
    const int dir = blockIdx.z;
    const int qi  = chunk * CBLOCK + threadIdx.x;
    const int lane = threadIdx.x & 31;
    const int wbase = threadIdx.x & ~31;
    const float* q  = (dir == 0) ? x : y;
    const float* db = (dir == 0) ? y : x;
    const float* qb  = q  + (size_t)b * NPTS * 3;
    const float* dbb = db + (size_t)b * NPTS * 3;

    // Coalesced split-min: 16 independent loads, tree-reduced for ILP.
    const int gq = (dir * BATCH + b) * NPTS + qi;
    unsigned long long v[SPLITS];
    #pragma unroll
    for (int s = 0; s < SPLITS; s++)
        v[s] = g_pack[(size_t)s * QTOTAL + gq];
    #pragma unroll
    for (int stride = SPLITS / 2; stride >= 1; stride >>= 1)
        #pragma unroll
        for (int s = 0; s < stride; s++)
            v[s] = (v[s + stride] < v[s]) ? v[s + stride] : v[s];
    const unsigned long long w = v[0];
    const float bb  = funmap((unsigned int)(w >> 32));
    const int  base = (int)(w & 0xFFFFFFFFu);

    const float qx = qb[qi*3+0], qy = qb[qi*3+1], qz = qb[qi*3+2];

    // Park per-query records in shared for intra-warp broadcast.
    __shared__ float4 sQ[CBLOCK];   // (nqx, nqy, nqz, bb)
    __shared__ int    sB[CBLOCK];   // 32-group base
    sQ[threadIdx.x] = make_float4(-qx, -qy, -qz, bb);
    sB[threadIdx.x] = base;
    __syncwarp();

    float nx = 0.f, ny = 0.f, nz = 0.f;

    // Depth-2 pipelined ballot rescan. Round ws serves the query of lane ws.
    float4 r0 = sQ[wbase + 0];
    int    c0 = sB[wbase + 0] + lane;
    float cx0 = dbb[c0*3+0], cy0 = dbb[c0*3+1], cz0 = dbb[c0*3+2];
    float4 r1 = sQ[wbase + 1];
    int    c1 = sB[wbase + 1] + lane;
    float cx1 = dbb[c1*3+0], cy1 = dbb[c1*3+1], cz1 = dbb[c1*3+2];

    #pragma unroll 4
    for (int ws = 0; ws < 32; ws++) {
        float4 r2; float cx2, cy2, cz2;
        if (ws < 30) {
            r2 = sQ[wbase + ws + 2];
            const int c2 = sB[wbase + ws + 2] + lane;
            cx2 = dbb[c2*3+0]; cy2 = dbb[c2*3+1]; cz2 = dbb[c2*3+2];
        }
        float d = score(cx0, cy0, cz0, r0.x, r0.y, r0.z);
        unsigned int mask = __ballot_sync(0xFFFFFFFFu, d == r0.w);
        const int first = __ffs(mask) - 1;   // >=0 guaranteed (bit-exact)
        // Winner lane's coords -> owner lane (first exact match = first min).
        float fx = __shfl_sync(0xFFFFFFFFu, cx0, first);
        float fy = __shfl_sync(0xFFFFFFFFu, cy0, first);
        float fz = __shfl_sync(0xFFFFFFFFu, cz0, first);
        if (lane == ws) { nx = fx; ny = fy; nz = fz; }
        r0 = r1; cx0 = cx1; cy0 = cy1; cz0 = cz1;
        r1 = r2; cx1 = cx2; cy1 = cy2; cz1 = cz2;
    }

    float ax = fabsf(qx - nx), ay = fabsf(qy - ny), az = fabsf(qz - nz);
    float ax2 = ax * ax, ay2 = ay * ay, az2 = az * az;
    float vsum = ax2 * ax2 * ax + ay2 * ay2 * ay + az2 * az2 * az;

    __shared__ float red[CBLOCK];
    red[threadIdx.x] = vsum;
    __syncthreads();
    __shared__ bool s_last;
    if (threadIdx.x < 32) {
        float rr = red[threadIdx.x] + red[threadIdx.x + 32]
                 + red[threadIdx.x + 64] + red[threadIdx.x + 96];
        #pragma unroll
        for (int off = 16; off > 0; off >>= 1)
            rr += __shfl_down_sync(0xFFFFFFFF, rr, off);
        if (threadIdx.x == 0) {
            g_part[(dir * BATCH + b) * QCHUNKS + chunk] = rr;
            __threadfence();
            unsigned int t = atomicAdd(&g_ticket, 1u);
            s_last = (t == NCOMBINE - 1);
        }
    }
    __syncthreads();

    if (s_last) {
        // Final reduction, fused into the last-arriving block.
        __shared__ float sp[NCOMBINE];
        __shared__ float roots[2 * BATCH];
        #pragma unroll
        for (int k = 0; k < NCOMBINE / CBLOCK; k++)
            sp[threadIdx.x + k * CBLOCK] = g_part[threadIdx.x + k * CBLOCK];
        __syncthreads();
        if (threadIdx.x < 2 * BATCH) {
            float s = 0.0f;
            #pragma unroll
            for (int c2 = 0; c2 < QCHUNKS; c2++) s += sp[threadIdx.x * QCHUNKS + c2];
            roots[threadIdx.x] = powf(s, 0.2f);
        }
        __syncthreads();
        if (threadIdx.x == 0) {
            float acc = 0.0f;
            #pragma unroll
            for (int i = 0; i < 2 * BATCH; i++) acc += roots[i];
            out[0] = acc / (float)BATCH;
            g_ticket = 0;   // reset for next graph replay (deterministic)
        }
    }
}

extern "C" void kernel_launch(void* const* d_in, const int* in_sizes, int n_in,
                              void* d_out, int out_size)
{
    const float* x = (const float*)d_in[0];
    const float* y = (const float*)d_in[1];
    float* out = (float*)d_out;

    dim3 grid(QCHUNKS_MAIN * SPLITS, BATCH, 2);   // 128 x 8 x 2 = 2048 blocks
    chamfer_main<<<grid, BLOCK>>>(x, y);

    dim3 cgrid(QCHUNKS, BATCH, 2);                // 32 x 8 x 2 = 512 blocks
    combine_kernel<<<cgrid, CBLOCK>>>(x, y, out);
}

// round 17
// speedup vs baseline: 1.0118x; 1.0118x over previous
#include <cuda_runtime.h>
#include <math.h>

#define BATCH   8
#define NPTS    4096
#define SPLITS  16
#define SCAND   (NPTS / SPLITS)   // 256 candidates per split = one tile
#define TILE    256
#define BLOCK   64
#define Q       8                 // queries per thread
#define QPB     (BLOCK * Q)       // 512 queries per block
#define QCHUNKS_MAIN (NPTS / QPB) // 8
#define CBLOCK  128               // combine threads per block
#define QCHUNKS (NPTS / CBLOCK)   // 32 combine chunks per (dir,b)
#define NCOMBINE (QCHUNKS * BATCH * 2)  // 512 combine blocks
#define QTOTAL  (2 * BATCH * NPTS)      // 65536 queries overall

// Scratch (static device arrays; no allocation allowed).
// Slim records (5B per query-split instead of 8B): u32 mapped score +
// u8 group index (SCAND/32 = 8 groups). Transposed [split][query] so all
// combine loads are lane-coalesced.
__device__ unsigned int  g_score[SPLITS * QTOTAL];
__device__ unsigned char g_gidx [SPLITS * QTOTAL];
__device__ float g_part[NCOMBINE];   // per-chunk |diff|^5 sums
__device__ unsigned int g_ticket;    // zero-init, self-resetting

// Order-preserving float -> uint32 map (monotone for all finite floats).
static __device__ __forceinline__ unsigned int fmap(float f) {
    unsigned int u = __float_as_uint(f);
    return (u & 0x80000000u) ? ~u : (u | 0x80000000u);
}
static __device__ __forceinline__ float funmap(unsigned int m) {
    return __uint_as_float((m & 0x80000000u) ? (m & 0x7FFFFFFFu) : ~m);
}

// Bit-exact rescore (identical fmaf sequence everywhere it is evaluated).
static __device__ __forceinline__ float score(float cx, float cy, float cz,
                                              float nqx, float nqy, float nqz) {
    float h = 0.5f * fmaf(cx, cx, fmaf(cy, cy, cz * cz));
    return fmaf(nqx, cx, fmaf(nqy, cy, fmaf(nqz, cz, h)));
}

// Main: each thread owns 8 queries, scans this block's 256-candidate split.
// Objective: h - q.c, h = 0.5|c|^2 (|q|^2 dropped, argmin-invariant).
// Hot loop BYTE-IDENTICAL to the proven floor kernel; only the epilogue
// stores changed (u32 score + u8 group index, both coalesced).
__global__ void __launch_bounds__(BLOCK) chamfer_main(
    const float* __restrict__ x, const float* __restrict__ y)
{
    const int qchunk = blockIdx.x >> 4;    // 0..7
    const int split  = blockIdx.x & 15;    // 0..15
    const int b   = blockIdx.y;
    const int dir = blockIdx.z;
    const float* q  = (dir == 0) ? x : y;
    const float* db = (dir == 0) ? y : x;
    const float* qb  = q  + (size_t)b * NPTS * 3;
    const float* dbb = db + (size_t)b * NPTS * 3;

    float nqx[Q], nqy[Q], nqz[Q];
    #pragma unroll
    for (int k = 0; k < Q; k++) {
        const int qi = qchunk * QPB + threadIdx.x + k * BLOCK;
        nqx[k] = -qb[qi*3+0];
        nqy[k] = -qb[qi*3+1];
        nqz[k] = -qb[qi*3+2];
    }

    __shared__ float4 sh[TILE];

    const int cbeg = split * SCAND;
    #pragma unroll
    for (int k = 0; k < TILE / BLOCK; k++) {
        const int cl = threadIdx.x + k * BLOCK;
        const int c  = cbeg + cl;
        float cx = dbb[c*3+0], cy = dbb[c*3+1], cz = dbb[c*3+2];
        sh[cl] = make_float4(cx, cy, cz, 0.5f * fmaf(cx, cx, fmaf(cy, cy, cz * cz)));
    }
    __syncthreads();

    float best[Q];
    int   base[Q];
    #pragma unroll
    for (int k = 0; k < Q; k++) { best[k] = 3.4e38f; base[k] = cbeg; }

    #pragma unroll
    for (int g = 0; g < TILE / 32; g++) {
        float prev[Q];
        #pragma unroll
        for (int k = 0; k < Q; k++) prev[k] = best[k];
        #pragma unroll 8
        for (int j = 0; j < 32; j++) {
            float4 c = sh[g * 32 + j];   // broadcast LDS.128, feeds 8 chains
            #pragma unroll
            for (int k = 0; k < Q; k++)
                best[k] = fminf(best[k],
                    fmaf(nqx[k], c.x, fmaf(nqy[k], c.y, fmaf(nqz[k], c.z, c.w))));
        }
        const int gb = cbeg + g * 32;
        #pragma unroll
        for (int k = 0; k < Q; k++)
            if (best[k] < prev[k]) base[k] = gb;   // strict <: earliest group wins
    }

    const int qs = (dir * BATCH + b) * NPTS;
    #pragma unroll
    for (int k = 0; k < Q; k++) {
        const int qi = qchunk * QPB + threadIdx.x + k * BLOCK;
        const size_t idx = (size_t)split * QTOTAL + qs + qi;
        g_score[idx] = fmap(best[k]);
        g_gidx[idx]  = (unsigned char)((base[k] - cbeg) >> 5);  // 0..7
    }
}

// Combine: split-min over 16 slim records. Ordering key per split:
//   ((u64)score32 << 16) | (split << 8) | gidx
// -> primary: score (bit-exact); tie: smaller split = earlier candidate range
// = first-min (gidx never decides; (q,split) unique). All 32 loads coalesced
// (u32: 512B/warp-pair, u8: 32B/warp) and independent. Then R15's ballot
// rescan (depth-1 pipeline) with in-round shfl NN extraction. Per-chunk
// reduction; LAST block (ticket) folds out[0].
__global__ void __launch_bounds__(CBLOCK) combine_kernel(
    const float* __restrict__ x, const float* __restrict__ y,
    float* __restrict__ out)
{
    const int chunk = blockIdx.x;
    const int b   = blockIdx.y;
    const int dir = blockIdx.z;
    const int qi  = chunk * CBLOCK + threadIdx.x;
    const int lane = threadIdx.x & 31;
    const int wbase = threadIdx.x & ~31;
    const float* q  = (dir == 0) ? x : y;
    const float* db = (dir == 0) ? y : x;
    const float* qb  = q  + (size_t)b * NPTS * 3;
    const float* dbb = db + (size_t)b * NPTS * 3;

    // Slim split-min: 16 independent u32 + 16 independent u8 loads, tree min.
    const int gq = (dir * BATCH + b) * NPTS + qi;
    unsigned long long v[SPLITS];
    #pragma unroll
    for (int s = 0; s < SPLITS; s++) {
        const size_t idx = (size_t)s * QTOTAL + gq;
        v[s] = ((unsigned long long)g_score[idx] << 16)
             | ((unsigned int)s << 8)
             | (unsigned int)g_gidx[idx];
    }
    #pragma unroll
    for (int stride = SPLITS / 2; stride >= 1; stride >>= 1)
        #pragma unroll
        for (int s = 0; s < stride; s++)
            v[s] = (v[s + stride] < v[s]) ? v[s + stride] : v[s];
    const unsigned long long w = v[0];
    const float bb   = funmap((unsigned int)(w >> 16));
    const int  wsplit = (int)((w >> 8) & 0xFFu);
    const int  base   = wsplit * SCAND + ((int)(w & 0xFFu) << 5);

    const float qx = qb[qi*3+0], qy = qb[qi*3+1], qz = qb[qi*3+2];

    // Park per-query records in shared for intra-warp broadcast.
    __shared__ float4 sQ[CBLOCK];   // (nqx, nqy, nqz, bb)
    __shared__ int    sB[CBLOCK];   // 32-group base
    sQ[threadIdx.x] = make_float4(-qx, -qy, -qz, bb);
    sB[threadIdx.x] = base;
    __syncwarp();

    float nx = 0.f, ny = 0.f, nz = 0.f;

    // Depth-1 pipelined ballot rescan (R15 champion form).
    float4 r  = sQ[wbase];
    int    c  = sB[wbase] + lane;
    float  cx = dbb[c*3+0], cy = dbb[c*3+1], cz = dbb[c*3+2];

    #pragma unroll 4
    for (int ws = 0; ws < 32; ws++) {
        float4 rn; float cxn, cyn, czn;
        if (ws < 31) {
            rn = sQ[wbase + ws + 1];
            const int cn = sB[wbase + ws + 1] + lane;
            cxn = dbb[cn*3+0]; cyn = dbb[cn*3+1]; czn = dbb[cn*3+2];
        }
        float d = score(cx, cy, cz, r.x, r.y, r.z);
        unsigned int mask = __ballot_sync(0xFFFFFFFFu, d == r.w);
        const int first = __ffs(mask) - 1;   // >=0 guaranteed (bit-exact)
        // Winner lane's coords -> owner lane (first exact match = first min).
        float fx = __shfl_sync(0xFFFFFFFFu, cx, first);
        float fy = __shfl_sync(0xFFFFFFFFu, cy, first);
        float fz = __shfl_sync(0xFFFFFFFFu, cz, first);
        if (lane == ws) { nx = fx; ny = fy; nz = fz; }
        r = rn; cx = cxn; cy = cyn; cz = czn;
    }

    float ax = fabsf(qx - nx), ay = fabsf(qy - ny), az = fabsf(qz - nz);
    float ax2 = ax * ax, ay2 = ay * ay, az2 = az * az;
    float vsum = ax2 * ax2 * ax + ay2 * ay2 * ay + az2 * az2 * az;

    __shared__ float red[CBLOCK];
    red[threadIdx.x] = vsum;
    __syncthreads();
    __shared__ bool s_last;
    if (threadIdx.x < 32) {
        float rr = red[threadIdx.x] + red[threadIdx.x + 32]
                 + red[threadIdx.x + 64] + red[threadIdx.x + 96];
        #pragma unroll
        for (int off = 16; off > 0; off >>= 1)
            rr += __shfl_down_sync(0xFFFFFFFF, rr, off);
        if (threadIdx.x == 0) {
            g_part[(dir * BATCH + b) * QCHUNKS + chunk] = rr;
            __threadfence();
            unsigned int t = atomicAdd(&g_ticket, 1u);
            s_last = (t == NCOMBINE - 1);
        }
    }
    __syncthreads();

    if (s_last) {
        // Final reduction, fused into the last-arriving block.
        __shared__ float sp[NCOMBINE];
        __shared__ float roots[2 * BATCH];
        #pragma unroll
        for (int k = 0; k < NCOMBINE / CBLOCK; k++)
            sp[threadIdx.x + k * CBLOCK] = g_part[threadIdx.x + k * CBLOCK];
        __syncthreads();
        if (threadIdx.x < 2 * BATCH) {
            float s = 0.0f;
            #pragma unroll
            for (int c2 = 0; c2 < QCHUNKS; c2++) s += sp[threadIdx.x * QCHUNKS + c2];
            roots[threadIdx.x] = powf(s, 0.2f);
        }
        __syncthreads();
        if (threadIdx.x == 0) {
            float acc = 0.0f;
            #pragma unroll
            for (int i = 0; i < 2 * BATCH; i++) acc += roots[i];
            out[0] = acc / (float)BATCH;
            g_ticket = 0;   // reset for next graph replay (deterministic)
        }
    }
}

extern "C" void kernel_launch(void* const* d_in, const int* in_sizes, int n_in,
                              void* d_out, int out_size)
{
    const float* x = (const float*)d_in[0];
    const float* y = (const float*)d_in[1];
    float* out = (float*)d_out;

    dim3 grid(QCHUNKS_MAIN * SPLITS, BATCH, 2);   // 128 x 8 x 2 = 2048 blocks
    chamfer_main<<<grid, BLOCK>>>(x, y);

    dim3 cgrid(QCHUNKS, BATCH, 2);                // 32 x 8 x 2 = 512 blocks
    combine_kernel<<<cgrid, CBLOCK>>>(x, y, out);
}